// round 13
// baseline (speedup 1.0000x reference)
#include <cuda_runtime.h>
#include <cuda_fp16.h>
#include <cstdint>

static constexpr int B_DIM = 8192;   // batch (GEMM M)
static constexpr int N_DIM = 2048;   // nodes / features (GEMM N and K)

// ---------------- scratch (device globals; allocation-free rule) ------------
__device__ __half g_Af[(size_t)B_DIM * N_DIM];       // A fp16 (8192 x 2048)
__device__ __half g_Wf[(size_t)N_DIM * N_DIM];       // W fp16

#define SW128(x) ((x) ^ (((x) >> 3) & 0x70))

// ---------------------------- PTX helpers (sm_80+ only) ---------------------
__device__ __forceinline__ uint32_t smem_u32(const void* p) {
    uint32_t a;
    asm("{ .reg .u64 t; cvta.to.shared.u64 t, %1; cvt.u32.u64 %0, t; }"
        : "=r"(a) : "l"(p));
    return a;
}

__device__ __forceinline__ void cp16(uint32_t saddr, const void* gaddr) {
    asm volatile("cp.async.cg.shared.global [%0], [%1], 16;"
                 :: "r"(saddr), "l"(gaddr) : "memory");
}
#define CP_COMMIT() asm volatile("cp.async.commit_group;" ::: "memory")
#define CP_WAIT(n)  asm volatile("cp.async.wait_group %0;" :: "n"(n) : "memory")
#define BAR_SYNC(id, cnt) \
    asm volatile("bar.sync %0, %1;" :: "r"(id), "r"(cnt) : "memory")

__device__ __forceinline__ void ldsm_x4(uint32_t* r, uint32_t addr) {
    asm volatile("ldmatrix.sync.aligned.m8n8.x4.shared.b16 {%0,%1,%2,%3}, [%4];"
                 : "=r"(r[0]), "=r"(r[1]), "=r"(r[2]), "=r"(r[3]) : "r"(addr));
}

__device__ __forceinline__ void mma_fp16(float* d, const uint32_t* a,
                                         const uint32_t* b) {
    asm volatile(
        "mma.sync.aligned.m16n8k16.row.col.f32.f16.f16.f32 "
        "{%0,%1,%2,%3}, {%4,%5,%6,%7}, {%8,%9}, {%0,%1,%2,%3};"
        : "+f"(d[0]), "+f"(d[1]), "+f"(d[2]), "+f"(d[3])
        : "r"(a[0]), "r"(a[1]), "r"(a[2]), "r"(a[3]), "r"(b[0]), "r"(b[1]));
}

// ---------------------------------------------------------------------------
// Kernel 1 (fused): build Af directly from x/label — no transposed copies.
// Block owns 16 batch rows r0..r0+15: stages x/label rows in smem (fp16,
// padded stride for conflict-free gathers), then for every q gathers the
// 8 adj columns and emits Af[q][r] = relu(conv) as fp16.
// ---------------------------------------------------------------------------
static constexpr int R_TILE = 16;
static constexpr int ROW_H  = 2052;                  // halves; 4104B, 8-aligned
static constexpr uint32_t FUSED_SMEM = 2u * R_TILE * ROW_H * 2;   // 131328 B

__global__ __launch_bounds__(256) void build_A_fused_kernel(
    const float* __restrict__ x, const float* __restrict__ label,
    const int* __restrict__ adj,
    const float* __restrict__ conv_w,
    const float* __restrict__ conv_b)
{
    extern __shared__ __half smh[];
    __half* xs = smh;                       // [R_TILE][ROW_H]
    __half* ls = smh + R_TILE * ROW_H;

    const int tid = threadIdx.x;
    const int r0  = blockIdx.x * R_TILE;

    // ---- load phase: 16 rows x 2048 floats per array, fp32 -> fp16 ----
#pragma unroll
    for (int i = 0; i < 32; i++) {          // 2*16*512 float4 / 256 thr = 64; 32 per array
        int idx = tid + i * 256;            // 0..8191
        int row = idx >> 9;                 // 0..15
        int c4  = idx & 511;                // float4 index in row
        float4 vx = __ldg((const float4*)(x     + (size_t)(r0 + row) * N_DIM) + c4);
        float4 vl = __ldg((const float4*)(label + (size_t)(r0 + row) * N_DIM) + c4);
        union { __half2 h[2]; uint2 u; } px, pl;
        px.h[0] = __floats2half2_rn(vx.x, vx.y);
        px.h[1] = __floats2half2_rn(vx.z, vx.w);
        pl.h[0] = __floats2half2_rn(vl.x, vl.y);
        pl.h[1] = __floats2half2_rn(vl.z, vl.w);
        *(uint2*)&xs[row * ROW_H + c4 * 4] = px.u;
        *(uint2*)&ls[row * ROW_H + c4 * 4] = pl.u;
    }
    __syncthreads();

    // ---- compute phase ----
    float w[8];
#pragma unroll
    for (int j = 0; j < 8; j++) w[j] = __ldg(&conv_w[j]);
    const float cb = __ldg(&conv_b[0]);

    const int rq    = tid & 15;             // r lane (16 consecutive outputs)
    const int qbase = tid >> 4;             // 0..15
    const __half* xr = xs + rq * ROW_H;
    const __half* lr = ls + rq * ROW_H;
    __half* outp = g_Af + r0 + rq;

#pragma unroll 2
    for (int qi = 0; qi < 128; qi++) {
        const int q = qbase + qi * 16;
        const int4 a4 = __ldg((const int4*)adj + q);

        float acc = cb;
        acc = fmaf(w[0], __half2float(xr[a4.x]), acc);
        acc = fmaf(w[1], __half2float(xr[a4.y]), acc);
        acc = fmaf(w[2], __half2float(xr[a4.z]), acc);
        acc = fmaf(w[3], __half2float(xr[a4.w]), acc);
        acc = fmaf(w[4], __half2float(lr[a4.x]), acc);
        acc = fmaf(w[5], __half2float(lr[a4.y]), acc);
        acc = fmaf(w[6], __half2float(lr[a4.z]), acc);
        acc = fmaf(w[7], __half2float(lr[a4.w]), acc);

        outp[(size_t)q * B_DIM] = __float2half_rn(fmaxf(acc, 0.f));
    }
}

// ---------------------------------------------------------------------------
// Kernel 2: convert lin_w to fp16
// ---------------------------------------------------------------------------
__global__ __launch_bounds__(256) void conv_W_kernel(const float* __restrict__ W)
{
    const size_t i = ((size_t)blockIdx.x * 256 + threadIdx.x) * 4;
    float4 v = __ldg((const float4*)(W + i));
    __half2* ph = (__half2*)&g_Wf[i];
    ph[0] = __floats2half2_rn(v.x, v.y);
    ph[1] = __floats2half2_rn(v.z, v.w);
}

// ---------------------------------------------------------------------------
// Kernel 3: mma.sync fp16 GEMM  C = Af @ Wf^T + b   (unchanged, best-known)
// CTA 128x128, 128 threads (4 warps 2m x 2n, warp tile 64x64), BK=64
// (SW128), 3 stages, 2 CTAs/SM, warp-owned tiles + 2-warp named barriers.
// ---------------------------------------------------------------------------
static constexpr int BM = 128, BN = 128, BK = 64;
static constexpr int NSTEP = N_DIM / BK;                 // 32
static constexpr int NSTAGE = 3;
static constexpr uint32_t TILE_B  = 64 * BK * 2;         // 8192 per 64-row tile
static constexpr uint32_t STAGE_B = 4 * TILE_B;          // 32768 (A0,A1,W0,W1)
static constexpr uint32_t GEMM_SMEM = NSTAGE * STAGE_B;  // 98304

struct Frag {
    uint32_t a[4][4];    // 4 m-frags
    uint32_t b[8][2];    // 8 n-frags
};

// ks XOR trick: chunk index lives in byte bits [4:6] and does not feed the
// SW128 swizzle mask, so off(ks) = off(0) ^ (ks << 5).
__device__ __forceinline__ void ld_frags(Frag& f, uint32_t st, int ks,
                                         const uint32_t* offA,
                                         const uint32_t* offB)
{
    const uint32_t kx = (uint32_t)ks << 5;
#pragma unroll
    for (int mf = 0; mf < 4; mf++)
        ldsm_x4(f.a[mf], st + (offA[mf] ^ kx));
#pragma unroll
    for (int g = 0; g < 4; g++) {
        uint32_t t[4];
        ldsm_x4(t, st + (offB[g] ^ kx));
        f.b[g * 2 + 0][0] = t[0]; f.b[g * 2 + 0][1] = t[2];
        f.b[g * 2 + 1][0] = t[1]; f.b[g * 2 + 1][1] = t[3];
    }
}

// each warp loads its own 64x128B tile slice for one stage (16 cp16/lane)
__device__ __forceinline__ void load_my_tile(uint32_t st_tile,
                                             const __half* src, int k0,
                                             int lane)
{
#pragma unroll
    for (int i = 0; i < 16; i++) {
        int idx = lane + i * 32;          // 0..511
        int row = idx >> 3, ch = idx & 7;
        uint32_t so = SW128((uint32_t)(row * 128 + ch * 16));
        cp16(st_tile + so, src + (size_t)row * N_DIM + k0 + ch * 8);
    }
}

__global__ __launch_bounds__(128, 2) void gemm_mma_kernel(
    const float* __restrict__ bias, float* __restrict__ C)
{
    extern __shared__ char smem[];
    const uint32_t sbase = smem_u32(smem);
    const int tid  = threadIdx.x;
    const int wid  = tid >> 5;
    const int lane = tid & 31;
    const int n0 = blockIdx.x * BN;
    const int m0 = blockIdx.y * BM;

    const int mg = wid >> 1;                // 0/1 (m half)
    const int ng = wid & 1;                 // 0/1 (n half)

    // tile ownership: w0->A0, w3->A1, w2->W0, w1->W1
    uint32_t my_off;  const __half* my_src;
    if      (wid == 0) { my_off = 0 * TILE_B; my_src = g_Af + (size_t)m0 * N_DIM; }
    else if (wid == 3) { my_off = 1 * TILE_B; my_src = g_Af + (size_t)(m0 + 64) * N_DIM; }
    else if (wid == 2) { my_off = 2 * TILE_B; my_src = g_Wf + (size_t)n0 * N_DIM; }
    else               { my_off = 3 * TILE_B; my_src = g_Wf + (size_t)(n0 + 64) * N_DIM; }

    const int barA = 1 + mg;     // {w00,w01} / {w10,w11}
    const int barW = 3 + ng;     // {w00,w10} / {w01,w11}

    // base swizzled LDSM offsets (ks = 0), local to the owning tile
    uint32_t offA[4], offB[4];
    {
        const int ch = lane >> 4;            // 0 or 1
        const uint32_t aoff = (uint32_t)mg * TILE_B;
        const uint32_t woff = (2u + (uint32_t)ng) * TILE_B;
#pragma unroll
        for (int mf = 0; mf < 4; mf++) {
            int row = mf * 16 + (lane & 15);
            offA[mf] = aoff + SW128((uint32_t)(row * 128 + ch * 16));
        }
#pragma unroll
        for (int g = 0; g < 4; g++) {
            int n = g * 16 + (lane & 15);
            offB[g] = woff + SW128((uint32_t)(n * 128 + ch * 16));
        }
    }

    float acc[4][8][4] = {};                // [m frag][n frag][reg]

    // prologue: each warp loads its own tile for stages 0 and 1
    load_my_tile(sbase + 0 * STAGE_B + my_off, my_src, 0,  lane); CP_COMMIT();
    load_my_tile(sbase + 1 * STAGE_B + my_off, my_src, BK, lane); CP_COMMIT();

    Frag f0, f1;

    for (int it = 0; it < NSTEP; ++it) {
        if (it + 1 < NSTEP) { CP_WAIT(1); } else { CP_WAIT(0); }
        BAR_SYNC(barA, 64);
        BAR_SYNC(barW, 64);

        if (it + 2 < NSTEP) {
            load_my_tile(sbase + (uint32_t)((it + 2) % NSTAGE) * STAGE_B + my_off,
                         my_src, (it + 2) * BK, lane);
            CP_COMMIT();
        }

        const uint32_t st = sbase + (uint32_t)(it % NSTAGE) * STAGE_B;

        ld_frags(f0, st, 0, offA, offB);
#pragma unroll
        for (int ks = 0; ks < 4; ks++) {
            Frag& cur = (ks & 1) ? f1 : f0;
            Frag& nxt = (ks & 1) ? f0 : f1;
            if (ks < 3) ld_frags(nxt, st, ks + 1, offA, offB);
#pragma unroll
            for (int mf = 0; mf < 4; mf++)
#pragma unroll
                for (int nf = 0; nf < 8; nf++)
                    mma_fp16(acc[mf][nf], cur.a[mf], cur.b[nf]);
        }
    }

    // ----- epilogue: hoisted bias, write C (warps disjoint) -----
    const int r_base = m0 + mg * 64 + (lane >> 2);
    const int c_base = n0 + ng * 64 + (lane & 3) * 2;
    float bb[8][2];
#pragma unroll
    for (int nf = 0; nf < 8; nf++) {
        bb[nf][0] = __ldg(&bias[c_base + nf * 8]);
        bb[nf][1] = __ldg(&bias[c_base + nf * 8 + 1]);
    }
#pragma unroll
    for (int mf = 0; mf < 4; mf++)
#pragma unroll
        for (int nf = 0; nf < 8; nf++) {
            int r = r_base + mf * 16;
            int c = c_base + nf * 8;
            float2 v0 = make_float2(acc[mf][nf][0] + bb[nf][0],
                                    acc[mf][nf][1] + bb[nf][1]);
            float2 v1 = make_float2(acc[mf][nf][2] + bb[nf][0],
                                    acc[mf][nf][3] + bb[nf][1]);
            *(float2*)&C[(size_t)r * N_DIM + c]       = v0;
            *(float2*)&C[(size_t)(r + 8) * N_DIM + c] = v1;
        }
}

// ---------------------------------------------------------------------------
extern "C" void kernel_launch(void* const* d_in, const int* in_sizes, int n_in,
                              void* d_out, int out_size)
{
    const float* x      = (const float*)d_in[0];
    const float* label  = (const float*)d_in[1];
    const int*   adj    = (const int*)  d_in[2];
    const float* conv_w = (const float*)d_in[3];
    const float* conv_b = (const float*)d_in[4];
    const float* lin_w  = (const float*)d_in[5];
    const float* lin_b  = (const float*)d_in[6];
    float* out = (float*)d_out;

    {   // 1) fused gather+conv: x/label -> Af directly (no transposed copies)
        cudaFuncSetAttribute(build_A_fused_kernel,
                             cudaFuncAttributeMaxDynamicSharedMemorySize,
                             FUSED_SMEM);
        build_A_fused_kernel<<<B_DIM / R_TILE, 256, FUSED_SMEM>>>(
            x, label, adj, conv_w, conv_b);
    }
    {   // 2) convert W to fp16
        conv_W_kernel<<<(N_DIM * N_DIM / 4) / 256, 256>>>(lin_w);
    }
    {   // 3) GEMM: warp-owned tiles + 2-warp named barriers, 2 CTAs/SM
        cudaFuncSetAttribute(gemm_mma_kernel,
                             cudaFuncAttributeMaxDynamicSharedMemorySize,
                             GEMM_SMEM);
        dim3 grid(N_DIM / BN, B_DIM / BM, 1);
        gemm_mma_kernel<<<grid, 128, GEMM_SMEM>>>(lin_b, out);
    }
}

// round 14
// speedup vs baseline: 1.0934x; 1.0934x over previous
#include <cuda_runtime.h>
#include <cuda_fp16.h>
#include <cstdint>

static constexpr int B_DIM = 8192;   // batch (GEMM M)
static constexpr int N_DIM = 2048;   // nodes / features (GEMM N and K)

// ---------------- scratch (device globals; allocation-free rule) ------------
__device__ __half g_Af[(size_t)B_DIM * N_DIM];       // A fp16 (8192 x 2048)
__device__ __half g_Wf[(size_t)N_DIM * N_DIM];       // W fp16

#define SW128(x) ((x) ^ (((x) >> 3) & 0x70))

// ---------------------------- PTX helpers (sm_80+ only) ---------------------
__device__ __forceinline__ uint32_t smem_u32(const void* p) {
    uint32_t a;
    asm("{ .reg .u64 t; cvta.to.shared.u64 t, %1; cvt.u32.u64 %0, t; }"
        : "=r"(a) : "l"(p));
    return a;
}

__device__ __forceinline__ void cp16(uint32_t saddr, const void* gaddr) {
    asm volatile("cp.async.cg.shared.global [%0], [%1], 16;"
                 :: "r"(saddr), "l"(gaddr) : "memory");
}
#define CP_COMMIT() asm volatile("cp.async.commit_group;" ::: "memory")
#define CP_WAIT(n)  asm volatile("cp.async.wait_group %0;" :: "n"(n) : "memory")
#define BAR_SYNC(id, cnt) \
    asm volatile("bar.sync %0, %1;" :: "r"(id), "r"(cnt) : "memory")

__device__ __forceinline__ void ldsm_x4(uint32_t* r, uint32_t addr) {
    asm volatile("ldmatrix.sync.aligned.m8n8.x4.shared.b16 {%0,%1,%2,%3}, [%4];"
                 : "=r"(r[0]), "=r"(r[1]), "=r"(r[2]), "=r"(r[3]) : "r"(addr));
}

__device__ __forceinline__ void mma_fp16(float* d, const uint32_t* a,
                                         const uint32_t* b) {
    asm volatile(
        "mma.sync.aligned.m16n8k16.row.col.f32.f16.f16.f32 "
        "{%0,%1,%2,%3}, {%4,%5,%6,%7}, {%8,%9}, {%0,%1,%2,%3};"
        : "+f"(d[0]), "+f"(d[1]), "+f"(d[2]), "+f"(d[3])
        : "r"(a[0]), "r"(a[1]), "r"(a[2]), "r"(a[3]), "r"(b[0]), "r"(b[1]));
}

// ---------------------------------------------------------------------------
// Kernel 1 (fused): build Af directly from x/label — no transposed copies.
// Block owns 8 batch rows r0..r0+7 (65.7KB smem -> 3 CTAs/SM so DRAM load
// phases of one CTA overlap gather phases of others). For every q, gathers
// the 8 adj columns from smem and emits Af[q][r] = relu(conv) as fp16.
// ---------------------------------------------------------------------------
static constexpr int R_TILE = 8;
static constexpr int ROW_H  = 2052;                  // halves; 4104B, 8-aligned
static constexpr uint32_t FUSED_SMEM = 2u * R_TILE * ROW_H * 2;   // 65664 B

__global__ __launch_bounds__(256) void build_A_fused_kernel(
    const float* __restrict__ x, const float* __restrict__ label,
    const int* __restrict__ adj,
    const float* __restrict__ conv_w,
    const float* __restrict__ conv_b)
{
    extern __shared__ __half smh[];
    __half* xs = smh;                       // [R_TILE][ROW_H]
    __half* ls = smh + R_TILE * ROW_H;

    const int tid = threadIdx.x;
    const int r0  = blockIdx.x * R_TILE;

    // ---- load phase: 8 rows x 2048 floats per array, fp32 -> fp16 ----
#pragma unroll
    for (int i = 0; i < 16; i++) {          // 8*512 float4 per array / 256 thr
        int idx = tid + i * 256;            // 0..4095
        int row = idx >> 9;                 // 0..7
        int c4  = idx & 511;                // float4 index in row
        float4 vx = __ldg((const float4*)(x     + (size_t)(r0 + row) * N_DIM) + c4);
        float4 vl = __ldg((const float4*)(label + (size_t)(r0 + row) * N_DIM) + c4);
        union { __half2 h[2]; uint2 u; } px, pl;
        px.h[0] = __floats2half2_rn(vx.x, vx.y);
        px.h[1] = __floats2half2_rn(vx.z, vx.w);
        pl.h[0] = __floats2half2_rn(vl.x, vl.y);
        pl.h[1] = __floats2half2_rn(vl.z, vl.w);
        *(uint2*)&xs[row * ROW_H + c4 * 4] = px.u;
        *(uint2*)&ls[row * ROW_H + c4 * 4] = pl.u;
    }
    __syncthreads();

    // ---- compute phase ----
    float w[8];
#pragma unroll
    for (int j = 0; j < 8; j++) w[j] = __ldg(&conv_w[j]);
    const float cb = __ldg(&conv_b[0]);

    const int rq    = tid & 7;              // r lane (8 consecutive outputs)
    const int qbase = tid >> 3;             // 0..31 (q stream)
    const __half* xr = xs + rq * ROW_H;
    const __half* lr = ls + rq * ROW_H;
    __half* outp = g_Af + r0 + rq;

    // adj double-buffer: keep next iteration's indices in flight
    int4 a4 = __ldg((const int4*)adj + qbase);
#pragma unroll 4
    for (int qi = 0; qi < 64; qi++) {
        const int q = qbase + qi * 32;
        const int4 cur = a4;
        if (qi + 1 < 64)
            a4 = __ldg((const int4*)adj + (qbase + (qi + 1) * 32));

        float acc = cb;
        acc = fmaf(w[0], __half2float(xr[cur.x]), acc);
        acc = fmaf(w[1], __half2float(xr[cur.y]), acc);
        acc = fmaf(w[2], __half2float(xr[cur.z]), acc);
        acc = fmaf(w[3], __half2float(xr[cur.w]), acc);
        acc = fmaf(w[4], __half2float(lr[cur.x]), acc);
        acc = fmaf(w[5], __half2float(lr[cur.y]), acc);
        acc = fmaf(w[6], __half2float(lr[cur.z]), acc);
        acc = fmaf(w[7], __half2float(lr[cur.w]), acc);

        outp[(size_t)q * B_DIM] = __float2half_rn(fmaxf(acc, 0.f));
    }
}

// ---------------------------------------------------------------------------
// Kernel 2: convert lin_w to fp16
// ---------------------------------------------------------------------------
__global__ __launch_bounds__(256) void conv_W_kernel(const float* __restrict__ W)
{
    const size_t i = ((size_t)blockIdx.x * 256 + threadIdx.x) * 4;
    float4 v = __ldg((const float4*)(W + i));
    __half2* ph = (__half2*)&g_Wf[i];
    ph[0] = __floats2half2_rn(v.x, v.y);
    ph[1] = __floats2half2_rn(v.z, v.w);
}

// ---------------------------------------------------------------------------
// Kernel 3: mma.sync fp16 GEMM  C = Af @ Wf^T + b   (unchanged, best-known)
// CTA 128x128, 128 threads (4 warps 2m x 2n, warp tile 64x64), BK=64
// (SW128), 3 stages, 2 CTAs/SM, warp-owned tiles + 2-warp named barriers.
// ---------------------------------------------------------------------------
static constexpr int BM = 128, BN = 128, BK = 64;
static constexpr int NSTEP = N_DIM / BK;                 // 32
static constexpr int NSTAGE = 3;
static constexpr uint32_t TILE_B  = 64 * BK * 2;         // 8192 per 64-row tile
static constexpr uint32_t STAGE_B = 4 * TILE_B;          // 32768 (A0,A1,W0,W1)
static constexpr uint32_t GEMM_SMEM = NSTAGE * STAGE_B;  // 98304

struct Frag {
    uint32_t a[4][4];    // 4 m-frags
    uint32_t b[8][2];    // 8 n-frags
};

// ks XOR trick: chunk index lives in byte bits [4:6] and does not feed the
// SW128 swizzle mask, so off(ks) = off(0) ^ (ks << 5).
__device__ __forceinline__ void ld_frags(Frag& f, uint32_t st, int ks,
                                         const uint32_t* offA,
                                         const uint32_t* offB)
{
    const uint32_t kx = (uint32_t)ks << 5;
#pragma unroll
    for (int mf = 0; mf < 4; mf++)
        ldsm_x4(f.a[mf], st + (offA[mf] ^ kx));
#pragma unroll
    for (int g = 0; g < 4; g++) {
        uint32_t t[4];
        ldsm_x4(t, st + (offB[g] ^ kx));
        f.b[g * 2 + 0][0] = t[0]; f.b[g * 2 + 0][1] = t[2];
        f.b[g * 2 + 1][0] = t[1]; f.b[g * 2 + 1][1] = t[3];
    }
}

// each warp loads its own 64x128B tile slice for one stage (16 cp16/lane)
__device__ __forceinline__ void load_my_tile(uint32_t st_tile,
                                             const __half* src, int k0,
                                             int lane)
{
#pragma unroll
    for (int i = 0; i < 16; i++) {
        int idx = lane + i * 32;          // 0..511
        int row = idx >> 3, ch = idx & 7;
        uint32_t so = SW128((uint32_t)(row * 128 + ch * 16));
        cp16(st_tile + so, src + (size_t)row * N_DIM + k0 + ch * 8);
    }
}

__global__ __launch_bounds__(128, 2) void gemm_mma_kernel(
    const float* __restrict__ bias, float* __restrict__ C)
{
    extern __shared__ char smem[];
    const uint32_t sbase = smem_u32(smem);
    const int tid  = threadIdx.x;
    const int wid  = tid >> 5;
    const int lane = tid & 31;
    const int n0 = blockIdx.x * BN;
    const int m0 = blockIdx.y * BM;

    const int mg = wid >> 1;                // 0/1 (m half)
    const int ng = wid & 1;                 // 0/1 (n half)

    // tile ownership: w0->A0, w3->A1, w2->W0, w1->W1
    uint32_t my_off;  const __half* my_src;
    if      (wid == 0) { my_off = 0 * TILE_B; my_src = g_Af + (size_t)m0 * N_DIM; }
    else if (wid == 3) { my_off = 1 * TILE_B; my_src = g_Af + (size_t)(m0 + 64) * N_DIM; }
    else if (wid == 2) { my_off = 2 * TILE_B; my_src = g_Wf + (size_t)n0 * N_DIM; }
    else               { my_off = 3 * TILE_B; my_src = g_Wf + (size_t)(n0 + 64) * N_DIM; }

    const int barA = 1 + mg;     // {w00,w01} / {w10,w11}
    const int barW = 3 + ng;     // {w00,w10} / {w01,w11}

    // base swizzled LDSM offsets (ks = 0), local to the owning tile
    uint32_t offA[4], offB[4];
    {
        const int ch = lane >> 4;            // 0 or 1
        const uint32_t aoff = (uint32_t)mg * TILE_B;
        const uint32_t woff = (2u + (uint32_t)ng) * TILE_B;
#pragma unroll
        for (int mf = 0; mf < 4; mf++) {
            int row = mf * 16 + (lane & 15);
            offA[mf] = aoff + SW128((uint32_t)(row * 128 + ch * 16));
        }
#pragma unroll
        for (int g = 0; g < 4; g++) {
            int n = g * 16 + (lane & 15);
            offB[g] = woff + SW128((uint32_t)(n * 128 + ch * 16));
        }
    }

    float acc[4][8][4] = {};                // [m frag][n frag][reg]

    // prologue: each warp loads its own tile for stages 0 and 1
    load_my_tile(sbase + 0 * STAGE_B + my_off, my_src, 0,  lane); CP_COMMIT();
    load_my_tile(sbase + 1 * STAGE_B + my_off, my_src, BK, lane); CP_COMMIT();

    Frag f0, f1;

    for (int it = 0; it < NSTEP; ++it) {
        if (it + 1 < NSTEP) { CP_WAIT(1); } else { CP_WAIT(0); }
        BAR_SYNC(barA, 64);
        BAR_SYNC(barW, 64);

        if (it + 2 < NSTEP) {
            load_my_tile(sbase + (uint32_t)((it + 2) % NSTAGE) * STAGE_B + my_off,
                         my_src, (it + 2) * BK, lane);
            CP_COMMIT();
        }

        const uint32_t st = sbase + (uint32_t)(it % NSTAGE) * STAGE_B;

        ld_frags(f0, st, 0, offA, offB);
#pragma unroll
        for (int ks = 0; ks < 4; ks++) {
            Frag& cur = (ks & 1) ? f1 : f0;
            Frag& nxt = (ks & 1) ? f0 : f1;
            if (ks < 3) ld_frags(nxt, st, ks + 1, offA, offB);
#pragma unroll
            for (int mf = 0; mf < 4; mf++)
#pragma unroll
                for (int nf = 0; nf < 8; nf++)
                    mma_fp16(acc[mf][nf], cur.a[mf], cur.b[nf]);
        }
    }

    // ----- epilogue: hoisted bias, write C (warps disjoint) -----
    const int r_base = m0 + mg * 64 + (lane >> 2);
    const int c_base = n0 + ng * 64 + (lane & 3) * 2;
    float bb[8][2];
#pragma unroll
    for (int nf = 0; nf < 8; nf++) {
        bb[nf][0] = __ldg(&bias[c_base + nf * 8]);
        bb[nf][1] = __ldg(&bias[c_base + nf * 8 + 1]);
    }
#pragma unroll
    for (int mf = 0; mf < 4; mf++)
#pragma unroll
        for (int nf = 0; nf < 8; nf++) {
            int r = r_base + mf * 16;
            int c = c_base + nf * 8;
            float2 v0 = make_float2(acc[mf][nf][0] + bb[nf][0],
                                    acc[mf][nf][1] + bb[nf][1]);
            float2 v1 = make_float2(acc[mf][nf][2] + bb[nf][0],
                                    acc[mf][nf][3] + bb[nf][1]);
            *(float2*)&C[(size_t)r * N_DIM + c]       = v0;
            *(float2*)&C[(size_t)(r + 8) * N_DIM + c] = v1;
        }
}

// ---------------------------------------------------------------------------
extern "C" void kernel_launch(void* const* d_in, const int* in_sizes, int n_in,
                              void* d_out, int out_size)
{
    const float* x      = (const float*)d_in[0];
    const float* label  = (const float*)d_in[1];
    const int*   adj    = (const int*)  d_in[2];
    const float* conv_w = (const float*)d_in[3];
    const float* conv_b = (const float*)d_in[4];
    const float* lin_w  = (const float*)d_in[5];
    const float* lin_b  = (const float*)d_in[6];
    float* out = (float*)d_out;

    {   // 1) fused gather+conv: x/label -> Af directly; 3 CTAs/SM overlap
        cudaFuncSetAttribute(build_A_fused_kernel,
                             cudaFuncAttributeMaxDynamicSharedMemorySize,
                             FUSED_SMEM);
        build_A_fused_kernel<<<B_DIM / R_TILE, 256, FUSED_SMEM>>>(
            x, label, adj, conv_w, conv_b);
    }
    {   // 2) convert W to fp16
        conv_W_kernel<<<(N_DIM * N_DIM / 4) / 256, 256>>>(lin_w);
    }
    {   // 3) GEMM: warp-owned tiles + 2-warp named barriers, 2 CTAs/SM
        cudaFuncSetAttribute(gemm_mma_kernel,
                             cudaFuncAttributeMaxDynamicSharedMemorySize,
                             GEMM_SMEM);
        dim3 grid(N_DIM / BN, B_DIM / BM, 1);
        gemm_mma_kernel<<<grid, 128, GEMM_SMEM>>>(lin_b, out);
    }
}

// round 15
// speedup vs baseline: 1.1784x; 1.0777x over previous
#include <cuda_runtime.h>
#include <cuda_fp16.h>
#include <cstdint>

static constexpr int B_DIM = 8192;   // batch (GEMM M)
static constexpr int N_DIM = 2048;   // nodes / features (GEMM N and K)

// ---------------- scratch (device globals; allocation-free rule) ------------
__device__ __half g_Af[(size_t)B_DIM * N_DIM];       // A fp16 (8192 x 2048)
__device__ __half g_Wf[(size_t)N_DIM * N_DIM];       // W fp16

#define SW128(x) ((x) ^ (((x) >> 3) & 0x70))

// ---------------------------- PTX helpers (sm_80+ only) ---------------------
__device__ __forceinline__ uint32_t smem_u32(const void* p) {
    uint32_t a;
    asm("{ .reg .u64 t; cvta.to.shared.u64 t, %1; cvt.u32.u64 %0, t; }"
        : "=r"(a) : "l"(p));
    return a;
}

__device__ __forceinline__ void cp16(uint32_t saddr, const void* gaddr) {
    asm volatile("cp.async.cg.shared.global [%0], [%1], 16;"
                 :: "r"(saddr), "l"(gaddr) : "memory");
}
#define CP_COMMIT() asm volatile("cp.async.commit_group;" ::: "memory")
#define CP_WAIT(n)  asm volatile("cp.async.wait_group %0;" :: "n"(n) : "memory")
#define BAR_SYNC(id, cnt) \
    asm volatile("bar.sync %0, %1;" :: "r"(id), "r"(cnt) : "memory")

__device__ __forceinline__ void ldsm_x4(uint32_t* r, uint32_t addr) {
    asm volatile("ldmatrix.sync.aligned.m8n8.x4.shared.b16 {%0,%1,%2,%3}, [%4];"
                 : "=r"(r[0]), "=r"(r[1]), "=r"(r[2]), "=r"(r[3]) : "r"(addr));
}

__device__ __forceinline__ void mma_fp16(float* d, const uint32_t* a,
                                         const uint32_t* b) {
    asm volatile(
        "mma.sync.aligned.m16n8k16.row.col.f32.f16.f16.f32 "
        "{%0,%1,%2,%3}, {%4,%5,%6,%7}, {%8,%9}, {%0,%1,%2,%3};"
        : "+f"(d[0]), "+f"(d[1]), "+f"(d[2]), "+f"(d[3])
        : "r"(a[0]), "r"(a[1]), "r"(a[2]), "r"(a[3]), "r"(b[0]), "r"(b[1]));
}

// ---------------------------------------------------------------------------
// Kernel 1 (fused): build Af directly from x/label.
// smem layout is COLUMN-major per 8-row tile: 16B chunk per node column
// holding that column's 8 batch-row values (fp16). One LDS.128 per gathered
// column yields all 8 outputs' operands. Column chunks are SW128-swizzled
// so the load-phase stores (lane l -> cols 4l+k) are bank-conflict-free.
// ---------------------------------------------------------------------------
static constexpr int R_TILE = 8;
static constexpr uint32_t ARR_B = (uint32_t)N_DIM * 16;      // 32768 per array
static constexpr uint32_t FUSED_SMEM = 2 * ARR_B;            // 65536

__device__ __forceinline__ void acc8(float* acc, uint4 g, float wj) {
    const __half2* h = (const __half2*)&g;
#pragma unroll
    for (int p = 0; p < 4; p++) {
        float2 v = __half22float2(h[p]);
        acc[2 * p + 0] = fmaf(wj, v.x, acc[2 * p + 0]);
        acc[2 * p + 1] = fmaf(wj, v.y, acc[2 * p + 1]);
    }
}

__global__ __launch_bounds__(256) void build_A_fused_kernel(
    const float* __restrict__ x, const float* __restrict__ label,
    const int* __restrict__ adj,
    const float* __restrict__ conv_w,
    const float* __restrict__ conv_b)
{
    extern __shared__ char smc[];
    char* xs = smc;
    char* ls = smc + ARR_B;

    const int tid = threadIdx.x;
    const int r0  = blockIdx.x * R_TILE;

    // ---- load phase: gather 8 rows per column quad, repack col-major ----
#pragma unroll
    for (int arr = 0; arr < 2; arr++) {
        const float* src = arr ? label : x;
        char* dst        = arr ? ls : xs;
#pragma unroll
        for (int j = 0; j < 2; j++) {
            const int cq = tid + j * 256;          // col-quad 0..511
            union { float4 v; float f[4]; } row[8];
#pragma unroll
            for (int r = 0; r < 8; r++)
                row[r].v = __ldg((const float4*)(src + (size_t)(r0 + r) * N_DIM) + cq);
#pragma unroll
            for (int k = 0; k < 4; k++) {
                const int c = cq * 4 + k;
                union { __half2 h[4]; uint4 u; } o;
                o.h[0] = __floats2half2_rn(row[0].f[k], row[1].f[k]);
                o.h[1] = __floats2half2_rn(row[2].f[k], row[3].f[k]);
                o.h[2] = __floats2half2_rn(row[4].f[k], row[5].f[k]);
                o.h[3] = __floats2half2_rn(row[6].f[k], row[7].f[k]);
                *(uint4*)(dst + SW128((uint32_t)(c * 16))) = o.u;
            }
        }
    }
    __syncthreads();

    // ---- compute phase: 1 q per thread per iteration, 8 outputs each ----
    float w[8];
#pragma unroll
    for (int j = 0; j < 8; j++) w[j] = __ldg(&conv_w[j]);
    const float cb = __ldg(&conv_b[0]);

#pragma unroll 2
    for (int qi = 0; qi < 8; qi++) {
        const int q = tid + qi * 256;
        const int4 a = __ldg((const int4*)adj + q);

        uint4 gx0 = *(uint4*)(xs + SW128((uint32_t)(a.x * 16)));
        uint4 gx1 = *(uint4*)(xs + SW128((uint32_t)(a.y * 16)));
        uint4 gx2 = *(uint4*)(xs + SW128((uint32_t)(a.z * 16)));
        uint4 gx3 = *(uint4*)(xs + SW128((uint32_t)(a.w * 16)));
        uint4 gl0 = *(uint4*)(ls + SW128((uint32_t)(a.x * 16)));
        uint4 gl1 = *(uint4*)(ls + SW128((uint32_t)(a.y * 16)));
        uint4 gl2 = *(uint4*)(ls + SW128((uint32_t)(a.z * 16)));
        uint4 gl3 = *(uint4*)(ls + SW128((uint32_t)(a.w * 16)));

        float acc[8];
#pragma unroll
        for (int r = 0; r < 8; r++) acc[r] = cb;
        acc8(acc, gx0, w[0]); acc8(acc, gx1, w[1]);
        acc8(acc, gx2, w[2]); acc8(acc, gx3, w[3]);
        acc8(acc, gl0, w[4]); acc8(acc, gl1, w[5]);
        acc8(acc, gl2, w[6]); acc8(acc, gl3, w[7]);

        union { __half2 h[4]; uint4 u; } o;
#pragma unroll
        for (int p = 0; p < 4; p++)
            o.h[p] = __floats2half2_rn(fmaxf(acc[2 * p], 0.f),
                                       fmaxf(acc[2 * p + 1], 0.f));
        *(uint4*)&g_Af[(size_t)q * B_DIM + r0] = o.u;
    }
}

// ---------------------------------------------------------------------------
// Kernel 2: convert lin_w to fp16
// ---------------------------------------------------------------------------
__global__ __launch_bounds__(256) void conv_W_kernel(const float* __restrict__ W)
{
    const size_t i = ((size_t)blockIdx.x * 256 + threadIdx.x) * 4;
    float4 v = __ldg((const float4*)(W + i));
    __half2* ph = (__half2*)&g_Wf[i];
    ph[0] = __floats2half2_rn(v.x, v.y);
    ph[1] = __floats2half2_rn(v.z, v.w);
}

// ---------------------------------------------------------------------------
// Kernel 3: mma.sync fp16 GEMM  C = Af @ Wf^T + b   (unchanged, best-known)
// CTA 128x128, 128 threads (4 warps 2m x 2n, warp tile 64x64), BK=64
// (SW128), 3 stages, 2 CTAs/SM, warp-owned tiles + 2-warp named barriers.
// ---------------------------------------------------------------------------
static constexpr int BM = 128, BN = 128, BK = 64;
static constexpr int NSTEP = N_DIM / BK;                 // 32
static constexpr int NSTAGE = 3;
static constexpr uint32_t TILE_B  = 64 * BK * 2;         // 8192 per 64-row tile
static constexpr uint32_t STAGE_B = 4 * TILE_B;          // 32768 (A0,A1,W0,W1)
static constexpr uint32_t GEMM_SMEM = NSTAGE * STAGE_B;  // 98304

struct Frag {
    uint32_t a[4][4];    // 4 m-frags
    uint32_t b[8][2];    // 8 n-frags
};

// ks XOR trick: chunk index lives in byte bits [4:6] and does not feed the
// SW128 swizzle mask, so off(ks) = off(0) ^ (ks << 5).
__device__ __forceinline__ void ld_frags(Frag& f, uint32_t st, int ks,
                                         const uint32_t* offA,
                                         const uint32_t* offB)
{
    const uint32_t kx = (uint32_t)ks << 5;
#pragma unroll
    for (int mf = 0; mf < 4; mf++)
        ldsm_x4(f.a[mf], st + (offA[mf] ^ kx));
#pragma unroll
    for (int g = 0; g < 4; g++) {
        uint32_t t[4];
        ldsm_x4(t, st + (offB[g] ^ kx));
        f.b[g * 2 + 0][0] = t[0]; f.b[g * 2 + 0][1] = t[2];
        f.b[g * 2 + 1][0] = t[1]; f.b[g * 2 + 1][1] = t[3];
    }
}

// each warp loads its own 64x128B tile slice for one stage (16 cp16/lane)
__device__ __forceinline__ void load_my_tile(uint32_t st_tile,
                                             const __half* src, int k0,
                                             int lane)
{
#pragma unroll
    for (int i = 0; i < 16; i++) {
        int idx = lane + i * 32;          // 0..511
        int row = idx >> 3, ch = idx & 7;
        uint32_t so = SW128((uint32_t)(row * 128 + ch * 16));
        cp16(st_tile + so, src + (size_t)row * N_DIM + k0 + ch * 8);
    }
}

__global__ __launch_bounds__(128, 2) void gemm_mma_kernel(
    const float* __restrict__ bias, float* __restrict__ C)
{
    extern __shared__ char smem[];
    const uint32_t sbase = smem_u32(smem);
    const int tid  = threadIdx.x;
    const int wid  = tid >> 5;
    const int lane = tid & 31;
    const int n0 = blockIdx.x * BN;
    const int m0 = blockIdx.y * BM;

    const int mg = wid >> 1;                // 0/1 (m half)
    const int ng = wid & 1;                 // 0/1 (n half)

    // tile ownership: w0->A0, w3->A1, w2->W0, w1->W1
    uint32_t my_off;  const __half* my_src;
    if      (wid == 0) { my_off = 0 * TILE_B; my_src = g_Af + (size_t)m0 * N_DIM; }
    else if (wid == 3) { my_off = 1 * TILE_B; my_src = g_Af + (size_t)(m0 + 64) * N_DIM; }
    else if (wid == 2) { my_off = 2 * TILE_B; my_src = g_Wf + (size_t)n0 * N_DIM; }
    else               { my_off = 3 * TILE_B; my_src = g_Wf + (size_t)(n0 + 64) * N_DIM; }

    const int barA = 1 + mg;     // {w00,w01} / {w10,w11}
    const int barW = 3 + ng;     // {w00,w10} / {w01,w11}

    // base swizzled LDSM offsets (ks = 0), local to the owning tile
    uint32_t offA[4], offB[4];
    {
        const int ch = lane >> 4;            // 0 or 1
        const uint32_t aoff = (uint32_t)mg * TILE_B;
        const uint32_t woff = (2u + (uint32_t)ng) * TILE_B;
#pragma unroll
        for (int mf = 0; mf < 4; mf++) {
            int row = mf * 16 + (lane & 15);
            offA[mf] = aoff + SW128((uint32_t)(row * 128 + ch * 16));
        }
#pragma unroll
        for (int g = 0; g < 4; g++) {
            int n = g * 16 + (lane & 15);
            offB[g] = woff + SW128((uint32_t)(n * 128 + ch * 16));
        }
    }

    float acc[4][8][4] = {};                // [m frag][n frag][reg]

    // prologue: each warp loads its own tile for stages 0 and 1
    load_my_tile(sbase + 0 * STAGE_B + my_off, my_src, 0,  lane); CP_COMMIT();
    load_my_tile(sbase + 1 * STAGE_B + my_off, my_src, BK, lane); CP_COMMIT();

    Frag f0, f1;

    for (int it = 0; it < NSTEP; ++it) {
        if (it + 1 < NSTEP) { CP_WAIT(1); } else { CP_WAIT(0); }
        BAR_SYNC(barA, 64);
        BAR_SYNC(barW, 64);

        if (it + 2 < NSTEP) {
            load_my_tile(sbase + (uint32_t)((it + 2) % NSTAGE) * STAGE_B + my_off,
                         my_src, (it + 2) * BK, lane);
            CP_COMMIT();
        }

        const uint32_t st = sbase + (uint32_t)(it % NSTAGE) * STAGE_B;

        ld_frags(f0, st, 0, offA, offB);
#pragma unroll
        for (int ks = 0; ks < 4; ks++) {
            Frag& cur = (ks & 1) ? f1 : f0;
            Frag& nxt = (ks & 1) ? f0 : f1;
            if (ks < 3) ld_frags(nxt, st, ks + 1, offA, offB);
#pragma unroll
            for (int mf = 0; mf < 4; mf++)
#pragma unroll
                for (int nf = 0; nf < 8; nf++)
                    mma_fp16(acc[mf][nf], cur.a[mf], cur.b[nf]);
        }
    }

    // ----- epilogue: hoisted bias, write C (warps disjoint) -----
    const int r_base = m0 + mg * 64 + (lane >> 2);
    const int c_base = n0 + ng * 64 + (lane & 3) * 2;
    float bb[8][2];
#pragma unroll
    for (int nf = 0; nf < 8; nf++) {
        bb[nf][0] = __ldg(&bias[c_base + nf * 8]);
        bb[nf][1] = __ldg(&bias[c_base + nf * 8 + 1]);
    }
#pragma unroll
    for (int mf = 0; mf < 4; mf++)
#pragma unroll
        for (int nf = 0; nf < 8; nf++) {
            int r = r_base + mf * 16;
            int c = c_base + nf * 8;
            float2 v0 = make_float2(acc[mf][nf][0] + bb[nf][0],
                                    acc[mf][nf][1] + bb[nf][1]);
            float2 v1 = make_float2(acc[mf][nf][2] + bb[nf][0],
                                    acc[mf][nf][3] + bb[nf][1]);
            *(float2*)&C[(size_t)r * N_DIM + c]       = v0;
            *(float2*)&C[(size_t)(r + 8) * N_DIM + c] = v1;
        }
}

// ---------------------------------------------------------------------------
extern "C" void kernel_launch(void* const* d_in, const int* in_sizes, int n_in,
                              void* d_out, int out_size)
{
    const float* x      = (const float*)d_in[0];
    const float* label  = (const float*)d_in[1];
    const int*   adj    = (const int*)  d_in[2];
    const float* conv_w = (const float*)d_in[3];
    const float* conv_b = (const float*)d_in[4];
    const float* lin_w  = (const float*)d_in[5];
    const float* lin_b  = (const float*)d_in[6];
    float* out = (float*)d_out;

    {   // 1) fused gather+conv: col-major smem tiles, LDS.128 gathers
        cudaFuncSetAttribute(build_A_fused_kernel,
                             cudaFuncAttributeMaxDynamicSharedMemorySize,
                             FUSED_SMEM);
        build_A_fused_kernel<<<B_DIM / R_TILE, 256, FUSED_SMEM>>>(
            x, label, adj, conv_w, conv_b);
    }
    {   // 2) convert W to fp16
        conv_W_kernel<<<(N_DIM * N_DIM / 4) / 256, 256>>>(lin_w);
    }
    {   // 3) GEMM: warp-owned tiles + 2-warp named barriers, 2 CTAs/SM
        cudaFuncSetAttribute(gemm_mma_kernel,
                             cudaFuncAttributeMaxDynamicSharedMemorySize,
                             GEMM_SMEM);
        dim3 grid(N_DIM / BN, B_DIM / BM, 1);
        gemm_mma_kernel<<<grid, 128, GEMM_SMEM>>>(lin_b, out);
    }
}

// round 16
// speedup vs baseline: 1.2019x; 1.0200x over previous
#include <cuda_runtime.h>
#include <cuda_fp16.h>
#include <cstdint>

static constexpr int B_DIM = 8192;   // batch (GEMM M)
static constexpr int N_DIM = 2048;   // nodes / features (GEMM N and K)

// ---------------- scratch (device globals; allocation-free rule) ------------
__device__ __half g_Af[(size_t)B_DIM * N_DIM];       // A fp16 (8192 x 2048)
__device__ __half g_Wf[(size_t)N_DIM * N_DIM];       // W fp16

#define SW128(x) ((x) ^ (((x) >> 3) & 0x70))

// ---------------------------- PTX helpers (sm_80+ only) ---------------------
__device__ __forceinline__ uint32_t smem_u32(const void* p) {
    uint32_t a;
    asm("{ .reg .u64 t; cvta.to.shared.u64 t, %1; cvt.u32.u64 %0, t; }"
        : "=r"(a) : "l"(p));
    return a;
}

__device__ __forceinline__ void cp16(uint32_t saddr, const void* gaddr) {
    asm volatile("cp.async.cg.shared.global [%0], [%1], 16;"
                 :: "r"(saddr), "l"(gaddr) : "memory");
}
#define CP_COMMIT() asm volatile("cp.async.commit_group;" ::: "memory")
#define CP_WAIT(n)  asm volatile("cp.async.wait_group %0;" :: "n"(n) : "memory")
#define BAR_SYNC(id, cnt) \
    asm volatile("bar.sync %0, %1;" :: "r"(id), "r"(cnt) : "memory")

__device__ __forceinline__ void ldsm_x4(uint32_t* r, uint32_t addr) {
    asm volatile("ldmatrix.sync.aligned.m8n8.x4.shared.b16 {%0,%1,%2,%3}, [%4];"
                 : "=r"(r[0]), "=r"(r[1]), "=r"(r[2]), "=r"(r[3]) : "r"(addr));
}

__device__ __forceinline__ void mma_fp16(float* d, const uint32_t* a,
                                         const uint32_t* b) {
    asm volatile(
        "mma.sync.aligned.m16n8k16.row.col.f32.f16.f16.f32 "
        "{%0,%1,%2,%3}, {%4,%5,%6,%7}, {%8,%9}, {%0,%1,%2,%3};"
        : "+f"(d[0]), "+f"(d[1]), "+f"(d[2]), "+f"(d[3])
        : "r"(a[0]), "r"(a[1]), "r"(a[2]), "r"(a[3]), "r"(b[0]), "r"(b[1]));
}

// ---------------------------------------------------------------------------
// Kernel 1 (merged): blocks [0, 2048)  -> fused gather+conv (4 batch rows),
//                    blocks [2048, ..) -> lin_w fp32->fp16 convert.
// Fused path: col-major smem chunks of 8B (4 r-values per node column) with
// pad-swizzle f(c) = c*8 + (c>>4)*8 (conflict-free repack stores).
// 6 CTAs/SM -> load/gather/write phases of different CTAs overlap.
// ---------------------------------------------------------------------------
static constexpr int R_TILE = 4;
static constexpr int FUSED_BLOCKS = B_DIM / R_TILE;              // 2048
static constexpr int CONVW_BLOCKS = (N_DIM * N_DIM / 4) / 256;   // 4096
static constexpr uint32_t ARR_B = (uint32_t)N_DIM * 8 + (N_DIM / 16) * 8; // 17408
static constexpr uint32_t FUSED_SMEM = 2 * ARR_B;                // 34816

__device__ __forceinline__ uint32_t colf(uint32_t c) {   // padded col offset
    return c * 8 + (c >> 4) * 8;
}

__device__ __forceinline__ void acc4(float* acc, uint2 g, float wj) {
    const __half2* h = (const __half2*)&g;
    float2 v0 = __half22float2(h[0]);
    float2 v1 = __half22float2(h[1]);
    acc[0] = fmaf(wj, v0.x, acc[0]);
    acc[1] = fmaf(wj, v0.y, acc[1]);
    acc[2] = fmaf(wj, v1.x, acc[2]);
    acc[3] = fmaf(wj, v1.y, acc[3]);
}

__global__ __launch_bounds__(256) void front_kernel(
    const float* __restrict__ x, const float* __restrict__ label,
    const int* __restrict__ adj,
    const float* __restrict__ conv_w,
    const float* __restrict__ conv_b,
    const float* __restrict__ W)
{
    const int tid = threadIdx.x;

    if (blockIdx.x >= FUSED_BLOCKS) {
        // ---- W convert path ----
        const int b = blockIdx.x - FUSED_BLOCKS;
        const size_t i = ((size_t)b * 256 + tid) * 4;
        float4 v = __ldg((const float4*)(W + i));
        __half2* ph = (__half2*)&g_Wf[i];
        ph[0] = __floats2half2_rn(v.x, v.y);
        ph[1] = __floats2half2_rn(v.z, v.w);
        return;
    }

    // ---- fused gather+conv path ----
    extern __shared__ char smc[];
    char* xs = smc;
    char* ls = smc + ARR_B;

    const int r0 = blockIdx.x * R_TILE;

    // load phase: 4 rows per array, repack col-major (4 r's per 8B chunk)
#pragma unroll
    for (int arr = 0; arr < 2; arr++) {
        const float* src = arr ? label : x;
        char* dst        = arr ? ls : xs;
#pragma unroll
        for (int j = 0; j < 2; j++) {
            const int cq = tid + j * 256;          // col-quad 0..511
            union { float4 v; float f[4]; } row[4];
#pragma unroll
            for (int r = 0; r < 4; r++)
                row[r].v = __ldg((const float4*)(src + (size_t)(r0 + r) * N_DIM) + cq);
#pragma unroll
            for (int k = 0; k < 4; k++) {
                const uint32_t c = cq * 4 + k;
                union { __half2 h[2]; uint2 u; } o;
                o.h[0] = __floats2half2_rn(row[0].f[k], row[1].f[k]);
                o.h[1] = __floats2half2_rn(row[2].f[k], row[3].f[k]);
                *(uint2*)(dst + colf(c)) = o.u;
            }
        }
    }
    __syncthreads();

    // compute phase: 1 q per thread per iteration, 4 outputs each
    float w[8];
#pragma unroll
    for (int j = 0; j < 8; j++) w[j] = __ldg(&conv_w[j]);
    const float cb = __ldg(&conv_b[0]);

#pragma unroll 4
    for (int qi = 0; qi < 8; qi++) {
        const int q = tid + qi * 256;
        const int4 a = __ldg((const int4*)adj + q);

        const uint32_t f0 = colf((uint32_t)a.x);
        const uint32_t f1 = colf((uint32_t)a.y);
        const uint32_t f2 = colf((uint32_t)a.z);
        const uint32_t f3 = colf((uint32_t)a.w);

        uint2 gx0 = *(uint2*)(xs + f0);
        uint2 gx1 = *(uint2*)(xs + f1);
        uint2 gx2 = *(uint2*)(xs + f2);
        uint2 gx3 = *(uint2*)(xs + f3);
        uint2 gl0 = *(uint2*)(ls + f0);
        uint2 gl1 = *(uint2*)(ls + f1);
        uint2 gl2 = *(uint2*)(ls + f2);
        uint2 gl3 = *(uint2*)(ls + f3);

        float acc[4] = {cb, cb, cb, cb};
        acc4(acc, gx0, w[0]); acc4(acc, gx1, w[1]);
        acc4(acc, gx2, w[2]); acc4(acc, gx3, w[3]);
        acc4(acc, gl0, w[4]); acc4(acc, gl1, w[5]);
        acc4(acc, gl2, w[6]); acc4(acc, gl3, w[7]);

        union { __half2 h[2]; uint2 u; } o;
        o.h[0] = __floats2half2_rn(fmaxf(acc[0], 0.f), fmaxf(acc[1], 0.f));
        o.h[1] = __floats2half2_rn(fmaxf(acc[2], 0.f), fmaxf(acc[3], 0.f));
        *(uint2*)&g_Af[(size_t)q * B_DIM + r0] = o.u;
    }
}

// ---------------------------------------------------------------------------
// Kernel 2: mma.sync fp16 GEMM  C = Af @ Wf^T + b   (unchanged, best-known)
// CTA 128x128, 128 threads (4 warps 2m x 2n, warp tile 64x64), BK=64
// (SW128), 3 stages, 2 CTAs/SM, warp-owned tiles + 2-warp named barriers.
// ---------------------------------------------------------------------------
static constexpr int BM = 128, BN = 128, BK = 64;
static constexpr int NSTEP = N_DIM / BK;                 // 32
static constexpr int NSTAGE = 3;
static constexpr uint32_t TILE_B  = 64 * BK * 2;         // 8192 per 64-row tile
static constexpr uint32_t STAGE_B = 4 * TILE_B;          // 32768 (A0,A1,W0,W1)
static constexpr uint32_t GEMM_SMEM = NSTAGE * STAGE_B;  // 98304

struct Frag {
    uint32_t a[4][4];    // 4 m-frags
    uint32_t b[8][2];    // 8 n-frags
};

// ks XOR trick: chunk index lives in byte bits [4:6] and does not feed the
// SW128 swizzle mask, so off(ks) = off(0) ^ (ks << 5).
__device__ __forceinline__ void ld_frags(Frag& f, uint32_t st, int ks,
                                         const uint32_t* offA,
                                         const uint32_t* offB)
{
    const uint32_t kx = (uint32_t)ks << 5;
#pragma unroll
    for (int mf = 0; mf < 4; mf++)
        ldsm_x4(f.a[mf], st + (offA[mf] ^ kx));
#pragma unroll
    for (int g = 0; g < 4; g++) {
        uint32_t t[4];
        ldsm_x4(t, st + (offB[g] ^ kx));
        f.b[g * 2 + 0][0] = t[0]; f.b[g * 2 + 0][1] = t[2];
        f.b[g * 2 + 1][0] = t[1]; f.b[g * 2 + 1][1] = t[3];
    }
}

// each warp loads its own 64x128B tile slice for one stage (16 cp16/lane)
__device__ __forceinline__ void load_my_tile(uint32_t st_tile,
                                             const __half* src, int k0,
                                             int lane)
{
#pragma unroll
    for (int i = 0; i < 16; i++) {
        int idx = lane + i * 32;          // 0..511
        int row = idx >> 3, ch = idx & 7;
        uint32_t so = SW128((uint32_t)(row * 128 + ch * 16));
        cp16(st_tile + so, src + (size_t)row * N_DIM + k0 + ch * 8);
    }
}

__global__ __launch_bounds__(128, 2) void gemm_mma_kernel(
    const float* __restrict__ bias, float* __restrict__ C)
{
    extern __shared__ char smem[];
    const uint32_t sbase = smem_u32(smem);
    const int tid  = threadIdx.x;
    const int wid  = tid >> 5;
    const int lane = tid & 31;
    const int n0 = blockIdx.x * BN;
    const int m0 = blockIdx.y * BM;

    const int mg = wid >> 1;                // 0/1 (m half)
    const int ng = wid & 1;                 // 0/1 (n half)

    // tile ownership: w0->A0, w3->A1, w2->W0, w1->W1
    uint32_t my_off;  const __half* my_src;
    if      (wid == 0) { my_off = 0 * TILE_B; my_src = g_Af + (size_t)m0 * N_DIM; }
    else if (wid == 3) { my_off = 1 * TILE_B; my_src = g_Af + (size_t)(m0 + 64) * N_DIM; }
    else if (wid == 2) { my_off = 2 * TILE_B; my_src = g_Wf + (size_t)n0 * N_DIM; }
    else               { my_off = 3 * TILE_B; my_src = g_Wf + (size_t)(n0 + 64) * N_DIM; }

    const int barA = 1 + mg;     // {w00,w01} / {w10,w11}
    const int barW = 3 + ng;     // {w00,w10} / {w01,w11}

    // base swizzled LDSM offsets (ks = 0), local to the owning tile
    uint32_t offA[4], offB[4];
    {
        const int ch = lane >> 4;            // 0 or 1
        const uint32_t aoff = (uint32_t)mg * TILE_B;
        const uint32_t woff = (2u + (uint32_t)ng) * TILE_B;
#pragma unroll
        for (int mf = 0; mf < 4; mf++) {
            int row = mf * 16 + (lane & 15);
            offA[mf] = aoff + SW128((uint32_t)(row * 128 + ch * 16));
        }
#pragma unroll
        for (int g = 0; g < 4; g++) {
            int n = g * 16 + (lane & 15);
            offB[g] = woff + SW128((uint32_t)(n * 128 + ch * 16));
        }
    }

    float acc[4][8][4] = {};                // [m frag][n frag][reg]

    // prologue: each warp loads its own tile for stages 0 and 1
    load_my_tile(sbase + 0 * STAGE_B + my_off, my_src, 0,  lane); CP_COMMIT();
    load_my_tile(sbase + 1 * STAGE_B + my_off, my_src, BK, lane); CP_COMMIT();

    Frag f0, f1;

    for (int it = 0; it < NSTEP; ++it) {
        if (it + 1 < NSTEP) { CP_WAIT(1); } else { CP_WAIT(0); }
        BAR_SYNC(barA, 64);
        BAR_SYNC(barW, 64);

        if (it + 2 < NSTEP) {
            load_my_tile(sbase + (uint32_t)((it + 2) % NSTAGE) * STAGE_B + my_off,
                         my_src, (it + 2) * BK, lane);
            CP_COMMIT();
        }

        const uint32_t st = sbase + (uint32_t)(it % NSTAGE) * STAGE_B;

        ld_frags(f0, st, 0, offA, offB);
#pragma unroll
        for (int ks = 0; ks < 4; ks++) {
            Frag& cur = (ks & 1) ? f1 : f0;
            Frag& nxt = (ks & 1) ? f0 : f1;
            if (ks < 3) ld_frags(nxt, st, ks + 1, offA, offB);
#pragma unroll
            for (int mf = 0; mf < 4; mf++)
#pragma unroll
                for (int nf = 0; nf < 8; nf++)
                    mma_fp16(acc[mf][nf], cur.a[mf], cur.b[nf]);
        }
    }

    // ----- epilogue: hoisted bias, write C (warps disjoint) -----
    const int r_base = m0 + mg * 64 + (lane >> 2);
    const int c_base = n0 + ng * 64 + (lane & 3) * 2;
    float bb[8][2];
#pragma unroll
    for (int nf = 0; nf < 8; nf++) {
        bb[nf][0] = __ldg(&bias[c_base + nf * 8]);
        bb[nf][1] = __ldg(&bias[c_base + nf * 8 + 1]);
    }
#pragma unroll
    for (int mf = 0; mf < 4; mf++)
#pragma unroll
        for (int nf = 0; nf < 8; nf++) {
            int r = r_base + mf * 16;
            int c = c_base + nf * 8;
            float2 v0 = make_float2(acc[mf][nf][0] + bb[nf][0],
                                    acc[mf][nf][1] + bb[nf][1]);
            float2 v1 = make_float2(acc[mf][nf][2] + bb[nf][0],
                                    acc[mf][nf][3] + bb[nf][1]);
            *(float2*)&C[(size_t)r * N_DIM + c]       = v0;
            *(float2*)&C[(size_t)(r + 8) * N_DIM + c] = v1;
        }
}

// ---------------------------------------------------------------------------
extern "C" void kernel_launch(void* const* d_in, const int* in_sizes, int n_in,
                              void* d_out, int out_size)
{
    const float* x      = (const float*)d_in[0];
    const float* label  = (const float*)d_in[1];
    const int*   adj    = (const int*)  d_in[2];
    const float* conv_w = (const float*)d_in[3];
    const float* conv_b = (const float*)d_in[4];
    const float* lin_w  = (const float*)d_in[5];
    const float* lin_b  = (const float*)d_in[6];
    float* out = (float*)d_out;

    {   // 1) merged front-end: fused gather+conv (6 CTAs/SM) + W convert
        cudaFuncSetAttribute(front_kernel,
                             cudaFuncAttributeMaxDynamicSharedMemorySize,
                             FUSED_SMEM);
        front_kernel<<<FUSED_BLOCKS + CONVW_BLOCKS, 256, FUSED_SMEM>>>(
            x, label, adj, conv_w, conv_b, lin_w);
    }
    {   // 2) GEMM: warp-owned tiles + 2-warp named barriers, 2 CTAs/SM
        cudaFuncSetAttribute(gemm_mma_kernel,
                             cudaFuncAttributeMaxDynamicSharedMemorySize,
                             GEMM_SMEM);
        dim3 grid(N_DIM / BN, B_DIM / BM, 1);
        gemm_mma_kernel<<<grid, 128, GEMM_SMEM>>>(lin_b, out);
    }
}